// round 5
// baseline (speedup 1.0000x reference)
#include <cuda_runtime.h>
#include <cuda_bf16.h>
#include <cuda_fp8.h>
#include <cstdint>

#define BATCH 4096
#define SEQ   19
#define EDIM  128
#define HDIM  1920
#define G4    7680
#define KTOT  2176
#define NTOK2 20

#define BK      64                   /* fp8 elems per stage col-block */
#define NIT     (KTOT / BK)          /* 34 */
#define ASTG_B  (64 * BK)            /* 4096  */
#define BSTG_B  (256 * BK)           /* 16384 */
#define STG_B   (ASTG_B + BSTG_B)    /* 20480 */
#define SMEM_BYTES (STG_B * 4)       /* 81920 */

#define SCALE_A 16.0f
#define SCALE_W 128.0f
#define INV_S   (1.0f / (SCALE_A * SCALE_W))

// ---------------- device scratch (static, no allocation) ----------------
__device__ uint8_t       g_W [(size_t)G4 * KTOT];          // e4m3, [7680][2176] = [W_ih|W_hh]*128
__device__ uint8_t       g_X [(size_t)SEQ * BATCH * 256];  // e4m3, x*16
__device__ uint8_t       g_H0[(size_t)BATCH * HDIM];       // e4m3 h ping (h*16)
__device__ uint8_t       g_H1[(size_t)BATCH * HDIM];       // e4m3 h pong
__device__ __nv_bfloat16 g_Hb[(size_t)BATCH * HDIM];       // exact h for k_final (last step)
__device__ float         g_C [(size_t)BATCH * HDIM];       // c state fp32

// ---------------- helpers ----------------
__device__ __forceinline__ uint32_t smem_u32(const void* p) {
    uint32_t a;
    asm("{ .reg .u64 t; cvta.to.shared.u64 t, %1; cvt.u32.u64 %0, t; }" : "=r"(a) : "l"(p));
    return a;
}
__device__ __forceinline__ void cp16(uint32_t saddr, const void* gaddr) {
    asm volatile("cp.async.cg.shared.global [%0], [%1], 16;" :: "r"(saddr), "l"(gaddr));
}
__device__ __forceinline__ uint32_t sw64(uint32_t off) { return off ^ ((off >> 3) & 0x30); }

__device__ __forceinline__ void ldsm_x4(uint32_t* r, uint32_t addr) {
    asm volatile("ldmatrix.sync.aligned.m8n8.x4.shared.b16 {%0,%1,%2,%3}, [%4];"
                 : "=r"(r[0]), "=r"(r[1]), "=r"(r[2]), "=r"(r[3]) : "r"(addr));
}
// fp8 e4m3 MMA, m16n8k32, f32 accum
__device__ __forceinline__ void mma_fp8(float* c, const uint32_t* a, const uint32_t* b) {
    asm volatile("mma.sync.aligned.m16n8k32.row.col.f32.e4m3.e4m3.f32 "
                 "{%0,%1,%2,%3}, {%4,%5,%6,%7}, {%8,%9}, {%0,%1,%2,%3};"
                 : "+f"(c[0]), "+f"(c[1]), "+f"(c[2]), "+f"(c[3])
                 : "r"(a[0]), "r"(a[1]), "r"(a[2]), "r"(a[3]), "r"(b[0]), "r"(b[1]));
}
__device__ __forceinline__ float sigm(float x)  { return 1.f / (1.f + __expf(-x)); }
__device__ __forceinline__ float tanh_f(float x){ return 2.f / (1.f + __expf(-2.f * x)) - 1.f; }
__device__ __forceinline__ uint8_t to_fp8(float v) {
    return (uint8_t)__nv_cvt_float_to_fp8(v, __NV_SATFINITE, __NV_E4M3);
}

// ---------------- prep kernels ----------------
__global__ void k_prep_w(const float* __restrict__ Wih, const float* __restrict__ Whh) {
    size_t n = (size_t)G4 * KTOT;
    for (size_t i = (size_t)blockIdx.x * blockDim.x + threadIdx.x; i < n;
         i += (size_t)gridDim.x * blockDim.x) {
        size_t r = i / KTOT; int k = (int)(i % KTOT);
        float v = (k < 256) ? Wih[r * 256 + k] : Whh[r * HDIM + (k - 256)];
        g_W[i] = to_fp8(v * SCALE_W);
    }
}
__global__ void k_prep_x(const int* __restrict__ in1, const float* __restrict__ emb,
                         const float* __restrict__ pos) {
    size_t n = (size_t)SEQ * BATCH * 256;
    for (size_t i = (size_t)blockIdx.x * blockDim.x + threadIdx.x; i < n;
         i += (size_t)gridDim.x * blockDim.x) {
        int e = (int)(i & 255);
        size_t bt = i >> 8;
        int b = (int)(bt & (BATCH - 1));
        int t = (int)(bt >> 12);
        float v = (e < 128) ? emb[(size_t)in1[b * SEQ + t] * EDIM + e]
                            : pos[t * EDIM + (e - 128)];
        g_X[i] = to_fp8(v * SCALE_A);
    }
}
__global__ void k_init() {
    size_t n = (size_t)BATCH * HDIM;
    size_t nq = n / 4;   // u32 words per fp8 h buffer
    for (size_t i = (size_t)blockIdx.x * blockDim.x + threadIdx.x; i < n;
         i += (size_t)gridDim.x * blockDim.x) {
        g_C[i] = 0.f;
        if (i < nq) {
            ((uint32_t*)g_H0)[i] = 0u;
            ((uint32_t*)g_H1)[i] = 0u;
        }
    }
}

// per-thread precomputed loader state (byte pointers, fp8 elements)
struct LoadCtx {
    const char* xp;
    const char* hp;
    const char* wp[4];
    uint32_t aoff;
    uint32_t boff[4];
};

__device__ __forceinline__ void load_stage(uint32_t stgB, int k0, const LoadCtx& L) {
    const char* ap = (k0 < 256) ? (L.xp + k0) : (L.hp + (k0 - 256));
    cp16(stgB + L.aoff, ap);
    uint32_t bB = stgB + ASTG_B;
    #pragma unroll
    for (int i = 0; i < 4; i++)
        cp16(bB + L.boff[i], L.wp[i] + k0);
}

// ---------------- LSTM step: pipelined fp8 mma.sync GEMM + fused cell ----------------
__global__ void __launch_bounds__(256, 2)
k_step(int t, const float* __restrict__ b_ih, const float* __restrict__ b_hh) {
    extern __shared__ __align__(128) char smem[];
    uint32_t sb = smem_u32(smem);
    int tid = threadIdx.x, lane = tid & 31, wid = tid >> 5;
    int wm = wid >> 2;          // 0..1  (M half: 32 rows each)
    int wn = wid & 3;           // 0..3  (16-channel slice)
    int m0 = blockIdx.x * 64;
    int j0 = blockIdx.y * 64;
    int bid = blockIdx.y * gridDim.x + blockIdx.x;
    int koff = ((bid / 148) & 1) ? (NIT / 2) : 0;

    const uint8_t* hsrc = (t & 1) ? g_H1 : g_H0;
    uint8_t*       hdst = (t & 1) ? g_H0 : g_H1;

    const uint8_t* xbase = g_X + ((size_t)t * BATCH + m0) * 256;
    const uint8_t* hbase = hsrc + (size_t)m0 * HDIM;
    const uint8_t* wbase = g_W + (size_t)j0 * KTOT;

    // ---- precompute per-thread load state ----
    LoadCtx L;
    {
        int r = tid >> 2, ch = tid & 3;      // A: 64 rows x 4 chunks of 16B
        L.aoff = sw64((uint32_t)(r * 64 + ch * 16));
        L.xp = (const char*)(xbase + (size_t)r * 256 + ch * 16);
        L.hp = (const char*)(hbase + (size_t)r * HDIM + ch * 16);
        #pragma unroll
        for (int i = 0; i < 4; i++) {        // B: 256 rows x 4 chunks of 16B
            int lin = tid + i * 256;
            int nrow = lin >> 2, bch = lin & 3;
            int grow = (nrow >> 6) * HDIM + (nrow & 63);
            L.boff[i] = sw64((uint32_t)(nrow * 64 + bch * 16));
            L.wp[i] = (const char*)(wbase + (size_t)grow * KTOT + bch * 16);
        }
    }

    // ---- precompute ldsm swizzled offsets (within stage) ----
    uint32_t af_off[2][2], bf_off[2][4];
    #pragma unroll
    for (int kk = 0; kk < 2; kk++) {
        int kb = kk * 32;                    // 32 bytes = k32 fp8
        #pragma unroll
        for (int mt = 0; mt < 2; mt++)
            af_off[kk][mt] = sw64((uint32_t)((wm * 32 + mt * 16 + (lane & 15)) * 64
                                             + kb + ((lane >> 4) * 16)));
        #pragma unroll
        for (int g = 0; g < 4; g++) {
            int nrow = g * 64 + wn * 16 + (lane & 7) + (((lane >> 4) & 1) * 8);
            bf_off[kk][g] = (uint32_t)(ASTG_B)
                          + sw64((uint32_t)(nrow * 64 + kb + (((lane >> 3) & 1) * 16)));
        }
    }

    float acc[2][4][2][4];      // [mt][gate][nt][frag]
    #pragma unroll
    for (int a = 0; a < 2; a++)
        #pragma unroll
        for (int b = 0; b < 4; b++)
            #pragma unroll
            for (int c = 0; c < 2; c++)
                #pragma unroll
                for (int d = 0; d < 4; d++) acc[a][b][c][d] = 0.f;

    auto kof = [&](int it) {
        int k = it + koff;
        if (k >= NIT) k -= NIT;
        return k * BK;
    };

    load_stage(sb + 0 * STG_B, kof(0), L);
    asm volatile("cp.async.commit_group;" ::: "memory");
    load_stage(sb + 1 * STG_B, kof(1), L);
    asm volatile("cp.async.commit_group;" ::: "memory");
    load_stage(sb + 2 * STG_B, kof(2), L);
    asm volatile("cp.async.commit_group;" ::: "memory");

    #pragma unroll 2
    for (int it = 0; it < NIT; it++) {
        asm volatile("cp.async.wait_group 2;" ::: "memory");
        __syncthreads();
        int pf = it + 3;
        if (pf < NIT) load_stage(sb + (pf & 3) * STG_B, kof(pf), L);
        asm volatile("cp.async.commit_group;" ::: "memory");

        uint32_t aB = sb + (it & 3) * STG_B;
        #pragma unroll
        for (int kk = 0; kk < 2; kk++) {
            uint32_t af[2][4], bf[4][4];
            #pragma unroll
            for (int mt = 0; mt < 2; mt++) ldsm_x4(af[mt], aB + af_off[kk][mt]);
            #pragma unroll
            for (int g = 0; g < 4; g++)   ldsm_x4(bf[g], aB + bf_off[kk][g]);
            #pragma unroll
            for (int mt = 0; mt < 2; mt++)
                #pragma unroll
                for (int g = 0; g < 4; g++) {
                    mma_fp8(acc[mt][g][0], af[mt], &bf[g][0]);
                    mma_fp8(acc[mt][g][1], af[mt], &bf[g][2]);
                }
        }
    }

    // ---------------- fused LSTM cell epilogue (in-register gates) ----------------
    int lq = lane & 3, lr = lane >> 2;
    float bias[4][2][2];
    #pragma unroll
    for (int g = 0; g < 4; g++)
        #pragma unroll
        for (int nt = 0; nt < 2; nt++)
            #pragma unroll
            for (int cc = 0; cc < 2; cc++) {
                int j = g * HDIM + j0 + wn * 16 + nt * 8 + lq * 2 + cc;
                bias[g][nt][cc] = b_ih[j] + b_hh[j];
            }

    bool last = (t == SEQ - 1);
    #pragma unroll
    for (int mt = 0; mt < 2; mt++)
        #pragma unroll
        for (int rh = 0; rh < 2; rh++) {
            int row = m0 + wm * 32 + mt * 16 + lr + rh * 8;
            size_t base = (size_t)row * HDIM + j0;
            #pragma unroll
            for (int nt = 0; nt < 2; nt++) {
                int ch = wn * 16 + nt * 8 + lq * 2;
                float2 cold = *(const float2*)(g_C + base + ch);
                float cn[2], hn[2];
                #pragma unroll
                for (int cc = 0; cc < 2; cc++) {
                    int fi = rh * 2 + cc;
                    float iv = sigm  (acc[mt][0][nt][fi] * INV_S + bias[0][nt][cc]);
                    float fv = sigm  (acc[mt][1][nt][fi] * INV_S + bias[1][nt][cc]);
                    float gv = tanh_f(acc[mt][2][nt][fi] * INV_S + bias[2][nt][cc]);
                    float ov = sigm  (acc[mt][3][nt][fi] * INV_S + bias[3][nt][cc]);
                    float co = cc ? cold.y : cold.x;
                    cn[cc] = fv * co + iv * gv;
                    hn[cc] = ov * tanh_f(cn[cc]);
                }
                *(float2*)(g_C + base + ch) = make_float2(cn[0], cn[1]);
                float2 hs = make_float2(hn[0] * SCALE_A, hn[1] * SCALE_A);
                __nv_fp8x2_storage_t hq =
                    __nv_cvt_float2_to_fp8x2(hs, __NV_SATFINITE, __NV_E4M3);
                *(uint16_t*)(hdst + base + ch) = (uint16_t)hq;
                if (last) {
                    __nv_bfloat162 hv;
                    hv.x = __float2bfloat16(hn[0]);
                    hv.y = __float2bfloat16(hn[1]);
                    *(__nv_bfloat162*)(g_Hb + base + ch) = hv;
                }
            }
        }
}

// ---------------- final: windowed einsum + max + log-softmax ----------------
__global__ void k_final(const int* __restrict__ in2, const float* __restrict__ emb,
                        const float* __restrict__ lw, const float* __restrict__ lb,
                        float* __restrict__ out) {
    int b = blockIdx.x;
    __shared__ __align__(16) float se[NTOK2 * 128];
    __shared__ __align__(16) float shv[HDIM];
    __shared__ float sd[300];
    __shared__ float sred[4];
    int tid = threadIdx.x;  // 128 threads

    for (int i = tid; i < NTOK2 * 128; i += 128) {
        int n = i >> 7, e = i & 127;
        se[i] = emb[(size_t)in2[b * NTOK2 + n] * EDIM + e];
    }
    for (int i = tid; i < HDIM; i += 128)
        shv[i] = __bfloat162float(g_Hb[(size_t)b * HDIM + i]);
    __syncthreads();

    for (int p = tid; p < 300; p += 128) {       // dotE[m][tok], m<15, tok<20
        int m = p / 20, n = p % 20;
        const float4* hv = (const float4*)(shv + m * 128);
        const float4* ev = (const float4*)(se + n * 128);
        float accv = 0.f;
        #pragma unroll
        for (int e = 0; e < 32; e++) {
            float4 a = hv[e], c = ev[e];
            accv = fmaf(a.x, c.x, fmaf(a.y, c.y, fmaf(a.z, c.z, fmaf(a.w, c.w, accv))));
        }
        sd[p] = accv;
    }
    __syncthreads();

    float mx = -3.4e38f;
    for (int p = tid; p < 90; p += 128) {
        int k = p / 18, n = p % 18;
        float rs = sd[(3 * k) * 20 + n] + sd[(3 * k + 1) * 20 + n + 1]
                 + sd[(3 * k + 2) * 20 + n + 2];
        mx = fmaxf(mx, rs);
    }
    #pragma unroll
    for (int o = 16; o > 0; o >>= 1) mx = fmaxf(mx, __shfl_xor_sync(0xffffffffu, mx, o));
    if ((tid & 31) == 0) sred[tid >> 5] = mx;
    __syncthreads();
    if (tid == 0) {
        float ms = fmaxf(fmaxf(sred[0], sred[1]), fmaxf(sred[2], sred[3]));
        float l0 = ms * lw[0] + lb[0];
        float l1 = ms * lw[1] + lb[1];
        float m2 = fmaxf(l0, l1);
        float lse = m2 + logf(expf(l0 - m2) + expf(l1 - m2));
        out[b * 2 + 0] = l0 - lse;
        out[b * 2 + 1] = l1 - lse;
    }
}

// ---------------- launch ----------------
extern "C" void kernel_launch(void* const* d_in, const int* in_sizes, int n_in,
                              void* d_out, int out_size) {
    (void)in_sizes; (void)n_in; (void)out_size;
    const int*   input1 = (const int*)  d_in[0];
    const int*   input2 = (const int*)  d_in[1];
    const float* emb    = (const float*)d_in[2];
    const float* pos    = (const float*)d_in[3];
    const float* W_ih   = (const float*)d_in[4];
    const float* W_hh   = (const float*)d_in[5];
    const float* b_ih   = (const float*)d_in[6];
    const float* b_hh   = (const float*)d_in[7];
    const float* lin_w  = (const float*)d_in[8];
    const float* lin_b  = (const float*)d_in[9];
    float* out = (float*)d_out;

    cudaFuncSetAttribute(k_step, cudaFuncAttributeMaxDynamicSharedMemorySize, SMEM_BYTES);

    k_prep_w<<<2048, 256>>>(W_ih, W_hh);
    k_prep_x<<<2048, 256>>>(input1, emb, pos);
    k_init<<<2048, 256>>>();

    dim3 grid(64, 30);  // 64 M-tiles x 30 J-tiles
    for (int t = 0; t < SEQ; t++)
        k_step<<<grid, 256, SMEM_BYTES>>>(t, b_ih, b_hh);

    k_final<<<BATCH, 128>>>(input2, emb, lin_w, lin_b, out);
}

// round 6
// speedup vs baseline: 1.0677x; 1.0677x over previous
#include <cuda_runtime.h>
#include <cuda_bf16.h>
#include <cstdint>

#define BATCH 4096
#define SEQ   19
#define EDIM  128
#define HDIM  1920
#define G4    7680
#define KTOT  2176
#define NTOK2 20

#define BK      64                   /* bf16 elems per K-block: 128B rows */
#define NIT     (KTOT / BK)          /* 34 */
#define ASTG_B  (64 * BK * 2)        /* 8192  */
#define BSTG_B  (256 * BK * 2)       /* 32768 */
#define STG_B   (ASTG_B + BSTG_B)    /* 40960 */
#define SMEM_BYTES (STG_B * 2)       /* 81920 */

// ---------------- device scratch (static, no allocation) ----------------
__device__ __nv_bfloat16 g_W [(size_t)G4 * KTOT];          // [7680][2176] = [W_ih | W_hh] bf16
__device__ __nv_bfloat16 g_X [(size_t)SEQ * BATCH * 256];  // per-step inputs [t][b][256]
__device__ __nv_bfloat16 g_H0[(size_t)BATCH * HDIM];       // h ping
__device__ __nv_bfloat16 g_H1[(size_t)BATCH * HDIM];       // h pong
__device__ float         g_C [(size_t)BATCH * HDIM];       // c state fp32

// ---------------- helpers ----------------
__device__ __forceinline__ uint32_t smem_u32(const void* p) {
    uint32_t a;
    asm("{ .reg .u64 t; cvta.to.shared.u64 t, %1; cvt.u32.u64 %0, t; }" : "=r"(a) : "l"(p));
    return a;
}
__device__ __forceinline__ void cp16(uint32_t saddr, const void* gaddr) {
    asm volatile("cp.async.cg.shared.global [%0], [%1], 16;" :: "r"(saddr), "l"(gaddr));
}
__device__ __forceinline__ uint32_t sw128(uint32_t off) { return off ^ ((off >> 3) & 0x70); }

__device__ __forceinline__ void ldsm_x4(uint32_t* r, uint32_t addr) {
    asm volatile("ldmatrix.sync.aligned.m8n8.x4.shared.b16 {%0,%1,%2,%3}, [%4];"
                 : "=r"(r[0]), "=r"(r[1]), "=r"(r[2]), "=r"(r[3]) : "r"(addr));
}
__device__ __forceinline__ void mma16816(float* c, const uint32_t* a, const uint32_t* b) {
    asm volatile("mma.sync.aligned.m16n8k16.row.col.f32.bf16.bf16.f32 "
                 "{%0,%1,%2,%3}, {%4,%5,%6,%7}, {%8,%9}, {%0,%1,%2,%3};"
                 : "+f"(c[0]), "+f"(c[1]), "+f"(c[2]), "+f"(c[3])
                 : "r"(a[0]), "r"(a[1]), "r"(a[2]), "r"(a[3]), "r"(b[0]), "r"(b[1]));
}
__device__ __forceinline__ float sigm(float x)  { return 1.f / (1.f + __expf(-x)); }
__device__ __forceinline__ float tanh_f(float x){ return 2.f / (1.f + __expf(-2.f * x)) - 1.f; }

// ---------------- prep kernels ----------------
__global__ void k_prep_w(const float* __restrict__ Wih, const float* __restrict__ Whh) {
    size_t n = (size_t)G4 * KTOT;
    for (size_t i = (size_t)blockIdx.x * blockDim.x + threadIdx.x; i < n;
         i += (size_t)gridDim.x * blockDim.x) {
        size_t r = i / KTOT; int k = (int)(i % KTOT);
        float v = (k < 256) ? Wih[r * 256 + k] : Whh[r * HDIM + (k - 256)];
        g_W[i] = __float2bfloat16(v);
    }
}
__global__ void k_prep_x(const int* __restrict__ in1, const float* __restrict__ emb,
                         const float* __restrict__ pos) {
    size_t n = (size_t)SEQ * BATCH * 256;
    for (size_t i = (size_t)blockIdx.x * blockDim.x + threadIdx.x; i < n;
         i += (size_t)gridDim.x * blockDim.x) {
        int e = (int)(i & 255);
        size_t bt = i >> 8;
        int b = (int)(bt & (BATCH - 1));
        int t = (int)(bt >> 12);
        float v = (e < 128) ? emb[(size_t)in1[b * SEQ + t] * EDIM + e]
                            : pos[t * EDIM + (e - 128)];
        g_X[i] = __float2bfloat16(v);
    }
}
__global__ void k_init() {
    size_t n = (size_t)BATCH * HDIM;
    size_t nh = n / 2;
    for (size_t i = (size_t)blockIdx.x * blockDim.x + threadIdx.x; i < n;
         i += (size_t)gridDim.x * blockDim.x) {
        g_C[i] = 0.f;
        if (i < nh) {
            ((uint32_t*)g_H0)[i] = 0u;
            ((uint32_t*)g_H1)[i] = 0u;
        }
    }
}

// per-thread precomputed loader state
struct LoadCtx {
    const char* xp;        // A src in g_X at col 0 (this thread's row/chunk)
    const char* hp;        // A src in hsrc at col 0
    const char* wp[4];     // B srcs at col 0
    uint32_t aoff[2];      // swizzled smem offsets of A chunks within stage
    uint32_t boff[8];      // swizzled smem offsets of B chunks within stage
};

__device__ __forceinline__ void load_stage(uint32_t stgB, int k0, const LoadCtx& L) {
    size_t kb = (size_t)k0 * 2;
    const char* ap = (k0 < 256) ? (L.xp + kb) : (L.hp + (size_t)(k0 - 256) * 2);
    // A: 64 rows x 128B, 2 chunks/thread (rows strided, cols within row)
    cp16(stgB + L.aoff[0], ap);
    cp16(stgB + L.aoff[1], ap + 32 * 256 * 0 + 0 * 0 + ( /* second chunk via ctx */ 0)); // placeholder (unused)
    uint32_t bB = stgB + ASTG_B;
    #pragma unroll
    for (int i = 0; i < 8; i++)
        cp16(bB + L.boff[i], L.wp[i & 3] + kb + (i >> 2) * 0);  // placeholder (unused)
}

// NOTE: load_stage above is replaced by an inline version in k_step (kept simple there).

// ---------------- LSTM step: pipelined bf16 mma.sync GEMM + fused cell ----------------
__global__ void __launch_bounds__(256, 2)
k_step(int t, const float* __restrict__ b_ih, const float* __restrict__ b_hh) {
    extern __shared__ __align__(128) char smem[];
    uint32_t sb = smem_u32(smem);
    int tid = threadIdx.x, lane = tid & 31, wid = tid >> 5;
    int wm = wid >> 2;          // 0..1  (M half: 32 rows each)
    int wn = wid & 3;           // 0..3  (16-channel slice)
    int m0 = blockIdx.x * 64;
    int j0 = blockIdx.y * 64;
    int bid = blockIdx.y * gridDim.x + blockIdx.x;
    int koff = ((bid / 148) & 1) ? (NIT / 2) : 0;

    const __nv_bfloat16* hsrc = (t & 1) ? g_H1 : g_H0;
    __nv_bfloat16*       hdst = (t & 1) ? g_H0 : g_H1;

    const __nv_bfloat16* xbase = g_X + ((size_t)t * BATCH + m0) * 256;
    const __nv_bfloat16* hbase = hsrc + (size_t)m0 * HDIM;
    const __nv_bfloat16* wbase = g_W + (size_t)j0 * KTOT;

    // ---- per-thread load state ----
    // A: 64 rows x 8 chunks(16B) = 512 chunks, 2 per thread
    int ar[2]; uint32_t aoff[2];
    const char* axp[2]; const char* ahp[2];
    #pragma unroll
    for (int i = 0; i < 2; i++) {
        int lin = tid + i * 256;
        int r = lin >> 3, ch = lin & 7;
        ar[i] = r;
        aoff[i] = sw128((uint32_t)(r * 128 + ch * 16));
        axp[i] = (const char*)(xbase + (size_t)r * 256 + ch * 8);
        ahp[i] = (const char*)(hbase + (size_t)r * HDIM + ch * 8);
    }
    // B: 256 rows x 8 chunks = 2048 chunks, 8 per thread
    uint32_t boff[8]; const char* bwp[8];
    #pragma unroll
    for (int i = 0; i < 8; i++) {
        int lin = tid + i * 256;
        int nrow = lin >> 3, ch = lin & 7;
        int grow = (nrow >> 6) * HDIM + (nrow & 63);
        boff[i] = sw128((uint32_t)(nrow * 128 + ch * 16));
        bwp[i] = (const char*)(wbase + (size_t)grow * KTOT + ch * 8);
    }

    // ---- ldsm swizzled base offsets (kk=0); per-kk addr = base ^ (kk*32) ----
    uint32_t af_b[2], bf_b[4];
    #pragma unroll
    for (int mt = 0; mt < 2; mt++)
        af_b[mt] = sw128((uint32_t)((wm * 32 + mt * 16 + (lane & 15)) * 128
                                    + ((lane >> 4) * 16)));
    #pragma unroll
    for (int g = 0; g < 4; g++) {
        int nrow = g * 64 + wn * 16 + (lane & 7) + (((lane >> 4) & 1) * 8);
        bf_b[g] = (uint32_t)ASTG_B
                + sw128((uint32_t)(nrow * 128 + (((lane >> 3) & 1) * 16)));
    }

    float acc[2][4][2][4];      // [mt][gate][nt][frag]
    #pragma unroll
    for (int a = 0; a < 2; a++)
        #pragma unroll
        for (int b = 0; b < 4; b++)
            #pragma unroll
            for (int c = 0; c < 2; c++)
                #pragma unroll
                for (int d = 0; d < 4; d++) acc[a][b][c][d] = 0.f;

    auto kof = [&](int it) {
        int k = it + koff;
        if (k >= NIT) k -= NIT;
        return k * BK;
    };
    auto issue_loads = [&](uint32_t stgB, int k0) {
        size_t kb = (size_t)k0 * 2;
        #pragma unroll
        for (int i = 0; i < 2; i++) {
            const char* ap = (k0 < 256) ? (axp[i] + kb)
                                        : (ahp[i] + (size_t)(k0 - 256) * 2);
            cp16(stgB + aoff[i], ap);
        }
        uint32_t bB = stgB + ASTG_B;
        #pragma unroll
        for (int i = 0; i < 8; i++)
            cp16(bB + boff[i], bwp[i] + kb);
    };

    // prologue: stage 0
    issue_loads(sb, kof(0));
    asm volatile("cp.async.commit_group;" ::: "memory");

    #pragma unroll 2
    for (int it = 0; it < NIT; it++) {
        // all warps done reading buffer (it+1)&1 (used in iter it-1), and
        // after wait below, stage it is ready & visible to all threads
        __syncthreads();
        int pf = it + 1;
        if (pf < NIT) issue_loads(sb + (pf & 1) * STG_B, kof(pf));
        asm volatile("cp.async.commit_group;" ::: "memory");
        asm volatile("cp.async.wait_group 1;" ::: "memory");
        __syncthreads();

        uint32_t aB = sb + (it & 1) * STG_B;
        #pragma unroll
        for (int kk = 0; kk < 4; kk++) {
            uint32_t kx = (uint32_t)(kk * 32);
            uint32_t af[2][4], bf[4][4];
            #pragma unroll
            for (int mt = 0; mt < 2; mt++) ldsm_x4(af[mt], aB + (af_b[mt] ^ kx));
            #pragma unroll
            for (int g = 0; g < 4; g++)   ldsm_x4(bf[g], aB + (bf_b[g] ^ kx));
            #pragma unroll
            for (int mt = 0; mt < 2; mt++)
                #pragma unroll
                for (int g = 0; g < 4; g++) {
                    mma16816(acc[mt][g][0], af[mt], &bf[g][0]);
                    mma16816(acc[mt][g][1], af[mt], &bf[g][2]);
                }
        }
    }

    // ---------------- fused LSTM cell epilogue (in-register gates) ----------------
    int lq = lane & 3, lr = lane >> 2;
    float bias[4][2][2];
    #pragma unroll
    for (int g = 0; g < 4; g++)
        #pragma unroll
        for (int nt = 0; nt < 2; nt++)
            #pragma unroll
            for (int cc = 0; cc < 2; cc++) {
                int j = g * HDIM + j0 + wn * 16 + nt * 8 + lq * 2 + cc;
                bias[g][nt][cc] = b_ih[j] + b_hh[j];
            }

    #pragma unroll
    for (int mt = 0; mt < 2; mt++)
        #pragma unroll
        for (int rh = 0; rh < 2; rh++) {
            int row = m0 + wm * 32 + mt * 16 + lr + rh * 8;
            size_t base = (size_t)row * HDIM + j0;
            #pragma unroll
            for (int nt = 0; nt < 2; nt++) {
                int ch = wn * 16 + nt * 8 + lq * 2;
                float2 cold = *(const float2*)(g_C + base + ch);
                float cn[2], hn[2];
                #pragma unroll
                for (int cc = 0; cc < 2; cc++) {
                    int fi = rh * 2 + cc;
                    float iv = sigm  (acc[mt][0][nt][fi] + bias[0][nt][cc]);
                    float fv = sigm  (acc[mt][1][nt][fi] + bias[1][nt][cc]);
                    float gv = tanh_f(acc[mt][2][nt][fi] + bias[2][nt][cc]);
                    float ov = sigm  (acc[mt][3][nt][fi] + bias[3][nt][cc]);
                    float co = cc ? cold.y : cold.x;
                    cn[cc] = fv * co + iv * gv;
                    hn[cc] = ov * tanh_f(cn[cc]);
                }
                *(float2*)(g_C + base + ch) = make_float2(cn[0], cn[1]);
                __nv_bfloat162 hv;
                hv.x = __float2bfloat16(hn[0]);
                hv.y = __float2bfloat16(hn[1]);
                *(__nv_bfloat162*)(hdst + base + ch) = hv;
            }
        }
}

// ---------------- final: windowed einsum + max + log-softmax ----------------
__global__ void k_final(const int* __restrict__ in2, const float* __restrict__ emb,
                        const float* __restrict__ lw, const float* __restrict__ lb,
                        float* __restrict__ out) {
    int b = blockIdx.x;
    __shared__ __align__(16) float se[NTOK2 * 128];
    __shared__ __align__(16) float shv[HDIM];
    __shared__ float sd[300];
    __shared__ float sred[4];
    int tid = threadIdx.x;  // 128 threads

    for (int i = tid; i < NTOK2 * 128; i += 128) {
        int n = i >> 7, e = i & 127;
        se[i] = emb[(size_t)in2[b * NTOK2 + n] * EDIM + e];
    }
    for (int i = tid; i < HDIM; i += 128)
        shv[i] = __bfloat162float(g_H1[(size_t)b * HDIM + i]);
    __syncthreads();

    for (int p = tid; p < 300; p += 128) {       // dotE[m][tok], m<15, tok<20
        int m = p / 20, n = p % 20;
        const float4* hv = (const float4*)(shv + m * 128);
        const float4* ev = (const float4*)(se + n * 128);
        float accv = 0.f;
        #pragma unroll
        for (int e = 0; e < 32; e++) {
            float4 a = hv[e], c = ev[e];
            accv = fmaf(a.x, c.x, fmaf(a.y, c.y, fmaf(a.z, c.z, fmaf(a.w, c.w, accv))));
        }
        sd[p] = accv;
    }
    __syncthreads();

    float mx = -3.4e38f;
    for (int p = tid; p < 90; p += 128) {
        int k = p / 18, n = p % 18;
        float rs = sd[(3 * k) * 20 + n] + sd[(3 * k + 1) * 20 + n + 1]
                 + sd[(3 * k + 2) * 20 + n + 2];
        mx = fmaxf(mx, rs);
    }
    #pragma unroll
    for (int o = 16; o > 0; o >>= 1) mx = fmaxf(mx, __shfl_xor_sync(0xffffffffu, mx, o));
    if ((tid & 31) == 0) sred[tid >> 5] = mx;
    __syncthreads();
    if (tid == 0) {
        float ms = fmaxf(fmaxf(sred[0], sred[1]), fmaxf(sred[2], sred[3]));
        float l0 = ms * lw[0] + lb[0];
        float l1 = ms * lw[1] + lb[1];
        float m2 = fmaxf(l0, l1);
        float lse = m2 + logf(expf(l0 - m2) + expf(l1 - m2));
        out[b * 2 + 0] = l0 - lse;
        out[b * 2 + 1] = l1 - lse;
    }
}

// ---------------- launch ----------------
extern "C" void kernel_launch(void* const* d_in, const int* in_sizes, int n_in,
                              void* d_out, int out_size) {
    (void)in_sizes; (void)n_in; (void)out_size;
    const int*   input1 = (const int*)  d_in[0];
    const int*   input2 = (const int*)  d_in[1];
    const float* emb    = (const float*)d_in[2];
    const float* pos    = (const float*)d_in[3];
    const float* W_ih   = (const float*)d_in[4];
    const float* W_hh   = (const float*)d_in[5];
    const float* b_ih   = (const float*)d_in[6];
    const float* b_hh   = (const float*)d_in[7];
    const float* lin_w  = (const float*)d_in[8];
    const float* lin_b  = (const float*)d_in[9];
    float* out = (float*)d_out;

    cudaFuncSetAttribute(k_step, cudaFuncAttributeMaxDynamicSharedMemorySize, SMEM_BYTES);

    k_prep_w<<<2048, 256>>>(W_ih, W_hh);
    k_prep_x<<<2048, 256>>>(input1, emb, pos);
    k_init<<<2048, 256>>>();

    dim3 grid(64, 30);  // 64 M-tiles x 30 J-tiles
    for (int t = 0; t < SEQ; t++)
        k_step<<<grid, 256, SMEM_BYTES>>>(t, b_ih, b_hh);

    k_final<<<BATCH, 128>>>(input2, emb, lin_w, lin_b, out);
}